// round 15
// baseline (speedup 1.0000x reference)
#include <cuda_runtime.h>
#include <cstdint>
#include <cstddef>

// ---------------- problem constants ----------------
#define MTOT 4096
#define NTOT 2048
#define K1   1024
#define K2   2048

#define BM 64
#define BN 128
#define BK 32
#define NS 2
#define NTHREADS 128

#define KT1  (K1 / BK)           // 32
#define KTOT ((K1 + K2) / BK)    // 96

#define STAGE_A  (BM * BK * 4)               // 8192 B
#define STAGE_B  (BN * BK * 4)               // 16384 B
#define STAGE_SZ (STAGE_A + STAGE_B)         // 24576 B
#define SMEM_BYTES (NS * STAGE_SZ)           // 49152 B -> 4 CTAs/SM, 512 thr/SM

// ---------------- scratch (__device__ globals: allocation-free) ----------------
__device__ float g_x [MTOT * (size_t)K1];
__device__ float g_h [MTOT * (size_t)K2];
__device__ float g_Wr[NTOT * (size_t)K1];
__device__ float g_Wz[NTOT * (size_t)K1];
__device__ float g_Wh[NTOT * (size_t)K1];
__device__ float g_Ur[NTOT * (size_t)K2];
__device__ float g_Uz[NTOT * (size_t)K2];
__device__ float g_Uh[NTOT * (size_t)K2];
__device__ float g_rh[MTOT * (size_t)NTOT];
__device__ float g_zb[MTOT * (size_t)NTOT];

// ---------------- helpers ----------------
__device__ __forceinline__ uint32_t smem_u32(const void* p) {
    uint32_t a;
    asm("{ .reg .u64 t; cvta.to.shared.u64 t, %1; cvt.u32.u64 %0, t; }" : "=r"(a) : "l"(p));
    return a;
}

__device__ __forceinline__ void cp16(uint32_t dst, const void* src) {
    asm volatile("cp.async.cg.shared.global [%0], [%1], 16;" :: "r"(dst), "l"(src));
}
__device__ __forceinline__ void cp_commit() {
    asm volatile("cp.async.commit_group;" ::: "memory");
}
__device__ __forceinline__ void cp_wait1() {
    asm volatile("cp.async.wait_group 1;" ::: "memory");
}

// ldmatrix x4 (b16): four 8x8 b16 matrices == four 8row x 4col fp32 tiles.
__device__ __forceinline__ void ldm4(uint32_t* r, uint32_t addr) {
    asm volatile("ldmatrix.sync.aligned.m8n8.x4.shared.b16 {%0,%1,%2,%3}, [%4];"
                 : "=r"(r[0]), "=r"(r[1]), "=r"(r[2]), "=r"(r[3]) : "r"(addr));
}

__device__ __forceinline__ void mma_tf32(float* c, const uint32_t* a, uint32_t b0, uint32_t b1) {
    asm volatile(
        "mma.sync.aligned.m16n8k8.row.col.f32.tf32.tf32.f32 "
        "{%0,%1,%2,%3}, {%4,%5,%6,%7}, {%8,%9}, {%0,%1,%2,%3};"
        : "+f"(c[0]), "+f"(c[1]), "+f"(c[2]), "+f"(c[3])
        : "r"(a[0]), "r"(a[1]), "r"(a[2]), "r"(a[3]), "r"(b0), "r"(b1));
}

__device__ __forceinline__ float tf32r(float x) {
    float r;
    asm("cvt.rna.tf32.f32 %0, %1;" : "=f"(r) : "f"(x));
    return r;
}
__device__ __forceinline__ float sigf(float v) { return 1.f / (1.f + __expf(-v)); }
__device__ __forceinline__ float tanhfast(float v) { return 2.f / (1.f + __expf(-2.f * v)) - 1.f; }

// ---------------- tf32 rounding pre-pass (one launch, 8 segments) ----------------
struct RoundSegs {
    const float4* src[8];
    float4*       dst[8];
    int           n4[8];
};

__global__ void round_all(RoundSegs S) {
    const int s = blockIdx.y;
    const float4* __restrict__ in = S.src[s];
    float4* __restrict__ out = S.dst[s];
    const int n4 = S.n4[s];
    for (int i = blockIdx.x * blockDim.x + threadIdx.x; i < n4; i += gridDim.x * blockDim.x) {
        float4 v = in[i];
        v.x = tf32r(v.x); v.y = tf32r(v.y); v.z = tf32r(v.z); v.w = tf32r(v.w);
        out[i] = v;
    }
}

// ---------------- tile loader (compile-time leading dimension) ----------------
// 128 threads: tr = tid>>3 (0..15), c = tid&7. A: 4 row-groups, B: 8 row-groups.
template <int LD>
__device__ __forceinline__ void load_seg(const float* __restrict__ pa,
                                         const float* __restrict__ pb,
                                         uint32_t st, uint32_t soff) {
#pragma unroll
    for (int i = 0; i < 4; i++)
        cp16(st + soff + i * 2048u, pa + (size_t)i * 16 * LD);
#pragma unroll
    for (int i = 0; i < 8; i++)
        cp16(st + STAGE_A + soff + i * 2048u, pb + (size_t)i * 16 * LD);
}

// ---------------- fused dual-source GEMM ----------------
// MODE 0 (fused r+z): grid 2048; N-half selects gate:
//   r: outr = tf32(sigmoid(acc+br) * hprev)   z: outz = sigmoid(acc+bz)
// MODE 1 (h): grid 1024; out = z*tanh(acc+bh) + (1-z)*hprev
template <int MODE>
__global__ void __launch_bounds__(NTHREADS, 4) gru_gemm(
    const float* __restrict__ A1, const float* __restrict__ A2,
    const float* __restrict__ B1r, const float* __restrict__ B2r,
    const float* __restrict__ B1z, const float* __restrict__ B2z,
    const float* __restrict__ biasr, const float* __restrict__ biasz,
    const float* __restrict__ hprev, const float* __restrict__ zbuf,
    float* __restrict__ outr, float* __restrict__ outz)
{
    extern __shared__ char smem[];
    const uint32_t sbase = smem_u32(smem);
    const int tid = threadIdx.x;
    const int wid = tid >> 5;
    const int lid = tid & 31;
    const int wm  = wid >> 1;     // 0..1 (M), 32 rows each
    const int wn  = wid & 1;      // 0..1 (N), 64 cols each
    const int bx  = blockIdx.x;
    const int tm  = bx & 63;      // fast dim -> B-tile sharing in L2

    int tn;
    bool zg = false;
    const float* B1;
    if (MODE == 0) {
        const int tnn = bx >> 6;              // 0..31
        zg = tnn >= 16;
        tn = tnn & 15;
        B1 = zg ? B1z : B1r;
    } else {
        tn = bx >> 6;                         // 0..15
        B1 = B1r;
    }

    // -------- loader per-thread constants --------
    const int tr = tid >> 3;                 // 0..15
    const int c  = tid & 7;                  // 16B chunk
    const uint32_t soff = (uint32_t)tr * 128u + (uint32_t)((c ^ (tr & 7)) << 4);

    const float* pa = A1 + (size_t)(tm * BM + tr) * K1 + c * 4;
    const float* pb = B1 + (size_t)(tn * BN + tr) * K1 + c * 4;

    // -------- ldmatrix addressing (lean) --------
    const int lr = lid & 7;
    const int mi = lid >> 3;
    const int lo = mi & 1;        // +8 rows
    const int hi = mi >> 1;       // +1 chunk (k+4)

    const uint32_t baseA = sbase + (uint32_t)(wm * 4096 + lo * 1024 + lr * 128);
    const uint32_t baseB = sbase + STAGE_A + (uint32_t)(wn * 8192 + lo * 1024 + lr * 128);

    float acc[2][8][4];
#pragma unroll
    for (int mt = 0; mt < 2; mt++)
#pragma unroll
        for (int nt = 0; nt < 8; nt++)
#pragma unroll
            for (int i = 0; i < 4; i++) acc[mt][nt][i] = 0.f;

    // -------- prologue: tile 0 into stage 0 --------
    load_seg<K1>(pa, pb, sbase, soff);
    pa += BK; pb += BK;
    cp_commit();

    // -------- mainloop (NS=2): 2 syncs per tile, pipelined fragments --------
#pragma unroll 1
    for (int kt0 = 0; kt0 < KTOT; kt0 += 2) {
#pragma unroll
        for (int s = 0; s < 2; s++) {
            const int kt = kt0 + s;
            const int lt = kt + 1;
            if (lt < KTOT) {
                if (lt == KT1) {   // switch to second K-source
                    pa = A2 + (size_t)(tm * BM + tr) * K2 + c * 4;
                    pb = (MODE == 0 ? (zg ? B2z : B2r) : B2r)
                         + (size_t)(tn * BN + tr) * K2 + c * 4;
                }
                const uint32_t st = sbase + (1 - s) * STAGE_SZ;
                if (lt < KT1) load_seg<K1>(pa, pb, st, soff);
                else          load_seg<K2>(pa, pb, st, soff);
                pa += BK; pb += BK;
            }
            cp_commit();         // uniform group accounting
            cp_wait1();          // own copies of tile kt complete
            __syncthreads();     // all 4 warps' copies of tile kt visible

            const uint32_t sA = baseA + s * STAGE_SZ;
            const uint32_t sB = baseB + s * STAGE_SZ;

            // fragment software pipeline: af ping-pong by q, bf ping-pong by j
            uint32_t af[2][2][4], bf[2][4];
            {
                const uint32_t o0 = (uint32_t)((hi ^ lr) << 4);   // q=0 chunk
                ldm4(af[0][0], sA + o0);
                ldm4(af[0][1], sA + 2048u + o0);
                ldm4(bf[0], sB + o0);
            }
#pragma unroll
            for (int q = 0; q < 4; q++) {
                const int pp = q & 1;
                const uint32_t oq  = (uint32_t)(((2 * q + hi) ^ lr) << 4);
                const uint32_t oqn = (uint32_t)(((2 * q + 2 + hi) ^ lr) << 4);
#pragma unroll
                for (int j = 0; j < 4; j++) {
                    const int cb = j & 1;
                    if (j < 3) {
                        ldm4(bf[cb ^ 1], sB + (uint32_t)((j + 1) * 2048) + oq);
                    } else if (q < 3) {
                        ldm4(af[pp ^ 1][0], sA + oqn);
                        ldm4(af[pp ^ 1][1], sA + 2048u + oqn);
                        ldm4(bf[cb ^ 1], sB + oqn);
                    }
                    mma_tf32(acc[0][2 * j + 0], af[pp][0], bf[cb][0], bf[cb][2]);
                    mma_tf32(acc[1][2 * j + 0], af[pp][1], bf[cb][0], bf[cb][2]);
                    mma_tf32(acc[0][2 * j + 1], af[pp][0], bf[cb][1], bf[cb][3]);
                    mma_tf32(acc[1][2 * j + 1], af[pp][1], bf[cb][1], bf[cb][3]);
                }
            }
            __syncthreads();     // computing done -> stage s may be reloaded
        }
    }

    // ---------------- epilogue ----------------
    const int g  = lid >> 2;
    const int tq = lid & 3;
    const float* bias = (MODE == 0) ? (zg ? biasz : biasr) : biasr;
    float* out        = (MODE == 0) ? (zg ? outz : outr) : outr;

#pragma unroll
    for (int mt = 0; mt < 2; mt++) {
#pragma unroll
        for (int nt = 0; nt < 8; nt++) {
            const int n = tn * BN + wn * 64 + nt * 8 + tq * 2;
            const float2 bi = *(const float2*)(bias + n);
#pragma unroll
            for (int half = 0; half < 2; half++) {
                const int m = tm * BM + wm * 32 + mt * 16 + g + half * 8;
                const size_t idx = (size_t)m * NTOT + n;
                float v0 = acc[mt][nt][half * 2 + 0] + bi.x;
                float v1 = acc[mt][nt][half * 2 + 1] + bi.y;
                float2 o;
                if (MODE == 0) {
                    const float s0 = sigf(v0), s1 = sigf(v1);
                    if (!zg) {
                        const float2 h = *(const float2*)(hprev + idx);
                        o.x = tf32r(s0 * h.x);
                        o.y = tf32r(s1 * h.y);
                    } else {
                        o.x = s0;
                        o.y = s1;
                    }
                } else {
                    const float2 h = *(const float2*)(hprev + idx);
                    const float2 z = *(const float2*)(zbuf + idx);
                    o.x = z.x * tanhfast(v0) + (1.f - z.x) * h.x;
                    o.y = z.y * tanhfast(v1) + (1.f - z.y) * h.y;
                }
                *(float2*)(out + idx) = o;
            }
        }
    }
}

// ---------------- host launcher ----------------
extern "C" void kernel_launch(void* const* d_in, const int* in_sizes, int n_in,
                              void* d_out, int out_size) {
    (void)in_sizes; (void)n_in; (void)out_size;
    // metadata order: x, hprev, Wh, Wz, Wr, Uh, Uz, Ur, bh, bz, br
    const float* x     = (const float*)d_in[0];
    const float* hprev = (const float*)d_in[1];
    const float* Wh    = (const float*)d_in[2];
    const float* Wz    = (const float*)d_in[3];
    const float* Wr    = (const float*)d_in[4];
    const float* Uh    = (const float*)d_in[5];
    const float* Uz    = (const float*)d_in[6];
    const float* Ur    = (const float*)d_in[7];
    const float* bh    = (const float*)d_in[8];
    const float* bz    = (const float*)d_in[9];
    const float* br    = (const float*)d_in[10];
    float* out = (float*)d_out;

    float *px, *ph, *pWr, *pWz, *pWh, *pUr, *pUz, *pUh, *prh, *pzb;
    cudaGetSymbolAddress((void**)&px,  g_x);
    cudaGetSymbolAddress((void**)&ph,  g_h);
    cudaGetSymbolAddress((void**)&pWr, g_Wr);
    cudaGetSymbolAddress((void**)&pWz, g_Wz);
    cudaGetSymbolAddress((void**)&pWh, g_Wh);
    cudaGetSymbolAddress((void**)&pUr, g_Ur);
    cudaGetSymbolAddress((void**)&pUz, g_Uz);
    cudaGetSymbolAddress((void**)&pUh, g_Uh);
    cudaGetSymbolAddress((void**)&prh, g_rh);
    cudaGetSymbolAddress((void**)&pzb, g_zb);

    cudaFuncSetAttribute(gru_gemm<0>, cudaFuncAttributeMaxDynamicSharedMemorySize, SMEM_BYTES);
    cudaFuncSetAttribute(gru_gemm<1>, cudaFuncAttributeMaxDynamicSharedMemorySize, SMEM_BYTES);

    // tf32 pre-round all GEMM operands into scratch (one launch)
    RoundSegs S;
    S.src[0] = (const float4*)x;     S.dst[0] = (float4*)px;  S.n4[0] = MTOT * K1 / 4;
    S.src[1] = (const float4*)hprev; S.dst[1] = (float4*)ph;  S.n4[1] = MTOT * K2 / 4;
    S.src[2] = (const float4*)Wr;    S.dst[2] = (float4*)pWr; S.n4[2] = NTOT * K1 / 4;
    S.src[3] = (const float4*)Wz;    S.dst[3] = (float4*)pWz; S.n4[3] = NTOT * K1 / 4;
    S.src[4] = (const float4*)Wh;    S.dst[4] = (float4*)pWh; S.n4[4] = NTOT * K1 / 4;
    S.src[5] = (const float4*)Ur;    S.dst[5] = (float4*)pUr; S.n4[5] = NTOT * K2 / 4;
    S.src[6] = (const float4*)Uz;    S.dst[6] = (float4*)pUz; S.n4[6] = NTOT * K2 / 4;
    S.src[7] = (const float4*)Uh;    S.dst[7] = (float4*)pUh; S.n4[7] = NTOT * K2 / 4;
    round_all<<<dim3(256, 8), 256>>>(S);

    const dim3 block(NTHREADS);
    // fused r+z: 2048 CTAs (N-half selects gate)
    gru_gemm<0><<<dim3(2048), block, SMEM_BYTES>>>(
        px, ph, pWr, pUr, pWz, pUz, br, bz, hprev, nullptr, prh, pzb);
    // h-gate: out = z * tanh(x@Wh^T + rh@Uh^T + bh) + (1-z) * hprev
    gru_gemm<1><<<dim3(1024), block, SMEM_BYTES>>>(
        px, prh, pWh, pUh, nullptr, nullptr, bh, nullptr, hprev, pzb, out, nullptr);
}